// round 3
// baseline (speedup 1.0000x reference)
#include <cuda_runtime.h>

#define N_NODES  50000
#define N_EDGES  800000
#define IN_CH    128
#define HID      64
#define N_GRAPHS 512
#define OUT_CH   10

// ---------------- scratch (static device memory; no allocations) ------------
__device__ float g_bufA[N_NODES * HID];   // y0 / scratch
__device__ float g_bufB[N_NODES * HID];   // agg buffer (atomics target)
__device__ float g_bufC[N_NODES * HID];   // y1
__device__ float g_pooled[N_GRAPHS * HID];

// ============================================================================
// K1: y0 = x @ w0a   (K=128). Also zeroes bufB rows for this block and
//     (block 0) zeroes pooled.
// ============================================================================
__global__ void __launch_bounds__(256) gemm_in_kernel(
    const float* __restrict__ A, const float* __restrict__ W,
    float* __restrict__ out, float* __restrict__ aggz, float* __restrict__ pooled)
{
    __shared__ float sX[64][68];
    __shared__ float sW[64][64];

    const int tid = threadIdx.x;
    const int tc = tid & 15;
    const int tr = tid >> 4;
    const int row0 = blockIdx.x * 64;

    float acc[4][4] = {};

    for (int kc = 0; kc < IN_CH; kc += 64) {
#pragma unroll
        for (int i = 0; i < 16; ++i) {
            int idx = tid + i * 256;
            int k = idx >> 6, c = idx & 63;
            sW[k][c] = W[(kc + k) * 64 + c];
        }
#pragma unroll
        for (int i = 0; i < 16; ++i) {
            int idx = tid + i * 256;
            int r = idx >> 6, kk = idx & 63;
            int row = row0 + r;
            sX[r][kk] = (row < N_NODES) ? A[(size_t)row * IN_CH + kc + kk] : 0.f;
        }
        __syncthreads();

#pragma unroll
        for (int k = 0; k < 64; k += 4) {
            float4 wv0 = *(const float4*)&sW[k + 0][tc * 4];
            float4 wv1 = *(const float4*)&sW[k + 1][tc * 4];
            float4 wv2 = *(const float4*)&sW[k + 2][tc * 4];
            float4 wv3 = *(const float4*)&sW[k + 3][tc * 4];
#pragma unroll
            for (int i = 0; i < 4; ++i) {
                float4 xv = *(const float4*)&sX[tr * 4 + i][k];
                acc[i][0] += xv.x * wv0.x + xv.y * wv1.x + xv.z * wv2.x + xv.w * wv3.x;
                acc[i][1] += xv.x * wv0.y + xv.y * wv1.y + xv.z * wv2.y + xv.w * wv3.y;
                acc[i][2] += xv.x * wv0.z + xv.y * wv1.z + xv.z * wv2.z + xv.w * wv3.z;
                acc[i][3] += xv.x * wv0.w + xv.y * wv1.w + xv.z * wv2.w + xv.w * wv3.w;
            }
        }
        __syncthreads();
    }

#pragma unroll
    for (int i = 0; i < 4; ++i) {
        int row = row0 + tr * 4 + i;
        if (row < N_NODES)
            *(float4*)&out[(size_t)row * 64 + tc * 4] =
                make_float4(acc[i][0], acc[i][1], acc[i][2], acc[i][3]);
    }

    // zero agg buffer rows for this block (prepare layer-0 atomics)
    const float4 z4 = make_float4(0.f, 0.f, 0.f, 0.f);
#pragma unroll
    for (int i = 0; i < 4; ++i) {
        int idx = tid + i * 256;              // 0..1023 float4s = 64 rows * 16
        int row = row0 + (idx >> 4);
        if (row < N_NODES)
            *(float4*)&aggz[(size_t)row * 64 + (idx & 15) * 4] = z4;
    }
    if (blockIdx.x == 0) {
        for (int i = tid; i < N_GRAPHS * HID / 4; i += 256)
            ((float4*)pooled)[i] = z4;
    }
}

// ============================================================================
// K2/K4: edge aggregation  agg[dst] += y[src]   (int32 indices)
// ============================================================================
__global__ void __launch_bounds__(256) edge_agg_kernel(
    const float* __restrict__ y, const int* __restrict__ ei,
    float* __restrict__ agg)
{
    int t = blockIdx.x * blockDim.x + threadIdx.x;
    if (t >= N_EDGES * 16) return;
    int e  = t >> 4;
    int c4 = t & 15;
    int src = __ldg(&ei[e]);
    int dst = __ldg(&ei[N_EDGES + e]);
    float4 v = *(const float4*)(y + (size_t)src * 64 + c4 * 4);
    float* p = agg + (size_t)dst * 64 + c4 * 4;
    asm volatile("red.global.add.v4.f32 [%0], {%1,%2,%3,%4};"
                 :: "l"(p), "f"(v.x), "f"(v.y), "f"(v.z), "f"(v.w) : "memory");
}

// ============================================================================
// K3: fused double GEMM:
//     Z = relu((1+eps)*A + G + preb)          (combine, and zero G after read)
//     T = relu(Z @ Wb + bb)                   (GEMM1, staged in smem)
//     out = T @ Wn                            (GEMM2, next layer's first lin)
// ============================================================================
__global__ void __launch_bounds__(256) mlp_fuse_kernel(
    const float* __restrict__ A, float* __restrict__ G,
    const float* __restrict__ epsp, const float* __restrict__ preb,
    const float* __restrict__ Wb, const float* __restrict__ bb,
    const float* __restrict__ Wn, float* __restrict__ out)
{
    __shared__ float sX[64][68];
    __shared__ float sW[64][64];

    const int tid = threadIdx.x;
    const int tc = tid & 15;
    const int tr = tid >> 4;
    const int row0 = blockIdx.x * 64;
    const float epsf = 1.0f + epsp[0];
    const float4 z4 = make_float4(0.f, 0.f, 0.f, 0.f);

    // load Wb
#pragma unroll
    for (int i = 0; i < 16; ++i) {
        int idx = tid + i * 256;
        sW[idx >> 6][idx & 63] = Wb[idx];
    }
    // combine into sX; zero G behind us
#pragma unroll
    for (int i = 0; i < 16; ++i) {
        int idx = tid + i * 256;
        int r = idx >> 6, kk = idx & 63;
        int row = row0 + r;
        float v = 0.f;
        if (row < N_NODES) {
            size_t off = (size_t)row * 64 + kk;
            float a = A[off];
            float g = G[off];
            v = fmaxf(fmaf(epsf, a, g) + preb[kk], 0.f);
            G[off] = 0.f;
        }
        sX[r][kk] = v;
    }
    __syncthreads();

    float acc[4][4] = {};
#pragma unroll
    for (int k = 0; k < 64; k += 4) {
        float4 wv0 = *(const float4*)&sW[k + 0][tc * 4];
        float4 wv1 = *(const float4*)&sW[k + 1][tc * 4];
        float4 wv2 = *(const float4*)&sW[k + 2][tc * 4];
        float4 wv3 = *(const float4*)&sW[k + 3][tc * 4];
#pragma unroll
        for (int i = 0; i < 4; ++i) {
            float4 xv = *(const float4*)&sX[tr * 4 + i][k];
            acc[i][0] += xv.x * wv0.x + xv.y * wv1.x + xv.z * wv2.x + xv.w * wv3.x;
            acc[i][1] += xv.x * wv0.y + xv.y * wv1.y + xv.z * wv2.y + xv.w * wv3.y;
            acc[i][2] += xv.x * wv0.z + xv.y * wv1.z + xv.z * wv2.z + xv.w * wv3.z;
            acc[i][3] += xv.x * wv0.w + xv.y * wv1.w + xv.z * wv2.w + xv.w * wv3.w;
        }
    }
    __syncthreads();   // everyone done reading sX/sW

    // T = relu(acc + bb) -> sX ; load Wn -> sW
    {
        const float4 bv = *(const float4*)&bb[tc * 4];
#pragma unroll
        for (int i = 0; i < 4; ++i) {
            float4 t;
            t.x = fmaxf(acc[i][0] + bv.x, 0.f);
            t.y = fmaxf(acc[i][1] + bv.y, 0.f);
            t.z = fmaxf(acc[i][2] + bv.z, 0.f);
            t.w = fmaxf(acc[i][3] + bv.w, 0.f);
            *(float4*)&sX[tr * 4 + i][tc * 4] = t;
        }
    }
#pragma unroll
    for (int i = 0; i < 16; ++i) {
        int idx = tid + i * 256;
        sW[idx >> 6][idx & 63] = Wn[idx];
    }
    __syncthreads();

    float acc2[4][4] = {};
#pragma unroll
    for (int k = 0; k < 64; k += 4) {
        float4 wv0 = *(const float4*)&sW[k + 0][tc * 4];
        float4 wv1 = *(const float4*)&sW[k + 1][tc * 4];
        float4 wv2 = *(const float4*)&sW[k + 2][tc * 4];
        float4 wv3 = *(const float4*)&sW[k + 3][tc * 4];
#pragma unroll
        for (int i = 0; i < 4; ++i) {
            float4 xv = *(const float4*)&sX[tr * 4 + i][k];
            acc2[i][0] += xv.x * wv0.x + xv.y * wv1.x + xv.z * wv2.x + xv.w * wv3.x;
            acc2[i][1] += xv.x * wv0.y + xv.y * wv1.y + xv.z * wv2.y + xv.w * wv3.y;
            acc2[i][2] += xv.x * wv0.z + xv.y * wv1.z + xv.z * wv2.z + xv.w * wv3.z;
            acc2[i][3] += xv.x * wv0.w + xv.y * wv1.w + xv.z * wv2.w + xv.w * wv3.w;
        }
    }

#pragma unroll
    for (int i = 0; i < 4; ++i) {
        int row = row0 + tr * 4 + i;
        if (row < N_NODES)
            *(float4*)&out[(size_t)row * 64 + tc * 4] =
                make_float4(acc2[i][0], acc2[i][1], acc2[i][2], acc2[i][3]);
    }
}

// ============================================================================
// K5: final MLP + pool:  h1 = relu(relu((1+eps)*A + G + preb) @ Wb + bb)
//     pooled[batch[row]] += h1[row]  (h1 never hits global memory)
// ============================================================================
__global__ void __launch_bounds__(256) mlp_pool_kernel(
    const float* __restrict__ A, const float* __restrict__ G,
    const float* __restrict__ epsp, const float* __restrict__ preb,
    const float* __restrict__ Wb, const float* __restrict__ bb,
    const int* __restrict__ batch, float* __restrict__ pooled)
{
    __shared__ float sX[64][68];
    __shared__ float sW[64][64];

    const int tid = threadIdx.x;
    const int tc = tid & 15;
    const int tr = tid >> 4;
    const int row0 = blockIdx.x * 64;
    const float epsf = 1.0f + epsp[0];

#pragma unroll
    for (int i = 0; i < 16; ++i) {
        int idx = tid + i * 256;
        sW[idx >> 6][idx & 63] = Wb[idx];
    }
#pragma unroll
    for (int i = 0; i < 16; ++i) {
        int idx = tid + i * 256;
        int r = idx >> 6, kk = idx & 63;
        int row = row0 + r;
        float v = 0.f;
        if (row < N_NODES) {
            size_t off = (size_t)row * 64 + kk;
            v = fmaxf(fmaf(epsf, A[off], G[off]) + preb[kk], 0.f);
        }
        sX[r][kk] = v;
    }
    __syncthreads();

    float acc[4][4] = {};
#pragma unroll
    for (int k = 0; k < 64; k += 4) {
        float4 wv0 = *(const float4*)&sW[k + 0][tc * 4];
        float4 wv1 = *(const float4*)&sW[k + 1][tc * 4];
        float4 wv2 = *(const float4*)&sW[k + 2][tc * 4];
        float4 wv3 = *(const float4*)&sW[k + 3][tc * 4];
#pragma unroll
        for (int i = 0; i < 4; ++i) {
            float4 xv = *(const float4*)&sX[tr * 4 + i][k];
            acc[i][0] += xv.x * wv0.x + xv.y * wv1.x + xv.z * wv2.x + xv.w * wv3.x;
            acc[i][1] += xv.x * wv0.y + xv.y * wv1.y + xv.z * wv2.y + xv.w * wv3.y;
            acc[i][2] += xv.x * wv0.z + xv.y * wv1.z + xv.z * wv2.z + xv.w * wv3.z;
            acc[i][3] += xv.x * wv0.w + xv.y * wv1.w + xv.z * wv2.w + xv.w * wv3.w;
        }
    }

    const float4 bv = *(const float4*)&bb[tc * 4];
#pragma unroll
    for (int i = 0; i < 4; ++i) {
        int row = row0 + tr * 4 + i;
        if (row < N_NODES) {
            int g = __ldg(&batch[row]);
            float4 o;
            o.x = fmaxf(acc[i][0] + bv.x, 0.f);
            o.y = fmaxf(acc[i][1] + bv.y, 0.f);
            o.z = fmaxf(acc[i][2] + bv.z, 0.f);
            o.w = fmaxf(acc[i][3] + bv.w, 0.f);
            float* p = pooled + (size_t)g * 64 + tc * 4;
            asm volatile("red.global.add.v4.f32 [%0], {%1,%2,%3,%4};"
                         :: "l"(p), "f"(o.x), "f"(o.y), "f"(o.z), "f"(o.w) : "memory");
        }
    }
}

// ============================================================================
// K6: head: logits + log_softmax
// ============================================================================
__global__ void __launch_bounds__(256) head_kernel(
    const float* __restrict__ pooled, const float* __restrict__ fcw,
    const float* __restrict__ fcb, float* __restrict__ out)
{
    int g = blockIdx.x * blockDim.x + threadIdx.x;
    if (g >= N_GRAPHS) return;
    float logit[OUT_CH];
#pragma unroll
    for (int j = 0; j < OUT_CH; ++j) logit[j] = __ldg(&fcb[j]);
#pragma unroll 8
    for (int k = 0; k < HID; ++k) {
        float p = pooled[g * HID + k];
#pragma unroll
        for (int j = 0; j < OUT_CH; ++j)
            logit[j] += p * __ldg(&fcw[k * OUT_CH + j]);
    }
    float m = logit[0];
#pragma unroll
    for (int j = 1; j < OUT_CH; ++j) m = fmaxf(m, logit[j]);
    float s = 0.f;
#pragma unroll
    for (int j = 0; j < OUT_CH; ++j) s += __expf(logit[j] - m);
    float ls = m + logf(s);
#pragma unroll
    for (int j = 0; j < OUT_CH; ++j) out[g * OUT_CH + j] = logit[j] - ls;
}

// ---------------- launch ----------------------------------------------------
extern "C" void kernel_launch(void* const* d_in, const int* in_sizes, int n_in,
                              void* d_out, int out_size)
{
    const float* x    = (const float*)d_in[0];
    const int*   ei   = (const int*)d_in[1];
    const int*   batch= (const int*)d_in[2];
    const float* eps0 = (const float*)d_in[3];
    const float* w0a  = (const float*)d_in[4];
    const float* b0a  = (const float*)d_in[5];
    const float* w0b  = (const float*)d_in[6];
    const float* b0b  = (const float*)d_in[7];
    const float* eps1 = (const float*)d_in[8];
    const float* w1a  = (const float*)d_in[9];
    const float* b1a  = (const float*)d_in[10];
    const float* w1b  = (const float*)d_in[11];
    const float* b1b  = (const float*)d_in[12];
    const float* fcw  = (const float*)d_in[13];
    const float* fcb  = (const float*)d_in[14];
    float*       out  = (float*)d_out;

    float *bufA, *bufB, *bufC, *pooled;
    cudaGetSymbolAddress((void**)&bufA, g_bufA);
    cudaGetSymbolAddress((void**)&bufB, g_bufB);
    cudaGetSymbolAddress((void**)&bufC, g_bufC);
    cudaGetSymbolAddress((void**)&pooled, g_pooled);

    const int gemm_blocks = (N_NODES + 63) / 64;                 // 782
    const int edge_blocks = (N_EDGES * 16 + 255) / 256;

    // K1: y0 = x @ w0a ; zero bufB + pooled
    gemm_in_kernel<<<gemm_blocks, 256>>>(x, w0a, bufA, bufB, pooled);
    // K2: agg0 = scatter-add(y0)
    edge_agg_kernel<<<edge_blocks, 256>>>(bufA, ei, bufB);
    // K3: y1 = relu(relu(combine0) @ w0b + b0b) @ w1a ; re-zero bufB
    mlp_fuse_kernel<<<gemm_blocks, 256>>>(bufA, bufB, eps0, b0a, w0b, b0b, w1a, bufC);
    // K4: agg1 = scatter-add(y1)
    edge_agg_kernel<<<edge_blocks, 256>>>(bufC, ei, bufB);
    // K5: h1 = relu(relu(combine1) @ w1b + b1b) ; pool into pooled
    mlp_pool_kernel<<<gemm_blocks, 256>>>(bufC, bufB, eps1, b1a, w1b, b1b, batch, pooled);
    // K6: logits + log_softmax
    head_kernel<<<2, 256>>>(pooled, fcw, fcb, out);
}

// round 4
// speedup vs baseline: 1.0074x; 1.0074x over previous
#include <cuda_runtime.h>

#define N_NODES  50000
#define N_EDGES  800000
#define IN_CH    128
#define HID      64
#define N_GRAPHS 512
#define OUT_CH   10

// ---------------- scratch (static device memory; no allocations) ------------
__device__ float g_bufA[N_NODES * HID];   // y (pre-agg features)
__device__ float g_bufZ[N_NODES * HID];   // Z (combined, post-relu)
__device__ float g_bufT[N_NODES * HID];   // T (mid-MLP)
__device__ float g_pooled[N_GRAPHS * HID];
__device__ int   g_deg[N_NODES];
__device__ int   g_start[N_NODES + 1];
__device__ int   g_cursor[N_NODES];
__device__ int   g_srcs[N_EDGES];

// ============================================================================
// K1: y0 = x @ w0a  (K=128). Tail: zero deg histogram; block 0 zeroes pooled.
// ============================================================================
__global__ void __launch_bounds__(256) gemm_in_kernel(
    const float* __restrict__ A, const float* __restrict__ W,
    float* __restrict__ out, int* __restrict__ deg, float* __restrict__ pooled)
{
    __shared__ float sX[64][68];
    __shared__ float sW[64][64];

    const int tid = threadIdx.x;
    const int tc = tid & 15;
    const int tr = tid >> 4;
    const int row0 = blockIdx.x * 64;

    float acc[4][4] = {};

    for (int kc = 0; kc < IN_CH; kc += 64) {
#pragma unroll
        for (int i = 0; i < 16; ++i) {
            int idx = tid + i * 256;
            sW[idx >> 6][idx & 63] = W[(kc + (idx >> 6)) * 64 + (idx & 63)];
        }
#pragma unroll
        for (int i = 0; i < 16; ++i) {
            int idx = tid + i * 256;
            int r = idx >> 6, kk = idx & 63;
            int row = row0 + r;
            sX[r][kk] = (row < N_NODES) ? A[(size_t)row * IN_CH + kc + kk] : 0.f;
        }
        __syncthreads();

#pragma unroll
        for (int k = 0; k < 64; k += 4) {
            float4 wv0 = *(const float4*)&sW[k + 0][tc * 4];
            float4 wv1 = *(const float4*)&sW[k + 1][tc * 4];
            float4 wv2 = *(const float4*)&sW[k + 2][tc * 4];
            float4 wv3 = *(const float4*)&sW[k + 3][tc * 4];
#pragma unroll
            for (int i = 0; i < 4; ++i) {
                float4 xv = *(const float4*)&sX[tr * 4 + i][k];
                acc[i][0] += xv.x * wv0.x + xv.y * wv1.x + xv.z * wv2.x + xv.w * wv3.x;
                acc[i][1] += xv.x * wv0.y + xv.y * wv1.y + xv.z * wv2.y + xv.w * wv3.y;
                acc[i][2] += xv.x * wv0.z + xv.y * wv1.z + xv.z * wv2.z + xv.w * wv3.z;
                acc[i][3] += xv.x * wv0.w + xv.y * wv1.w + xv.z * wv2.w + xv.w * wv3.w;
            }
        }
        __syncthreads();
    }

#pragma unroll
    for (int i = 0; i < 4; ++i) {
        int row = row0 + tr * 4 + i;
        if (row < N_NODES)
            *(float4*)&out[(size_t)row * 64 + tc * 4] =
                make_float4(acc[i][0], acc[i][1], acc[i][2], acc[i][3]);
    }

    // zero degree histogram (782 blocks x 64 covers 50048 >= 50000)
    if (tid < 64) {
        int i = row0 + tid;
        if (i < N_NODES) deg[i] = 0;
    }
    if (blockIdx.x == 0) {
        const float4 z4 = make_float4(0.f, 0.f, 0.f, 0.f);
        for (int i = tid; i < N_GRAPHS * HID / 4; i += 256)
            ((float4*)pooled)[i] = z4;
    }
}

// ============================================================================
// CSR build
// ============================================================================
__global__ void __launch_bounds__(256) hist_kernel(
    const int* __restrict__ ei, int* __restrict__ deg)
{
    int e = blockIdx.x * blockDim.x + threadIdx.x;
    if (e >= N_EDGES) return;
    atomicAdd(&deg[__ldg(&ei[N_EDGES + e])], 1);
}

__global__ void __launch_bounds__(1024) scan_kernel(
    const int* __restrict__ deg, int* __restrict__ start, int* __restrict__ cursor)
{
    __shared__ int part[1024];
    const int tid = threadIdx.x;
    const int CHUNK = (N_NODES + 1023) / 1024;   // 49
    const int base = tid * CHUNK;

    int s = 0;
    for (int i = 0; i < CHUNK; ++i) {
        int idx = base + i;
        if (idx < N_NODES) s += deg[idx];
    }
    part[tid] = s;
    __syncthreads();
    // Hillis-Steele inclusive scan
    for (int off = 1; off < 1024; off <<= 1) {
        int v = (tid >= off) ? part[tid - off] : 0;
        __syncthreads();
        part[tid] += v;
        __syncthreads();
    }
    int run = part[tid] - s;   // exclusive prefix of this chunk
    for (int i = 0; i < CHUNK; ++i) {
        int idx = base + i;
        if (idx < N_NODES) {
            start[idx] = run;
            cursor[idx] = run;
            run += deg[idx];
        }
    }
    if (tid == 1023) start[N_NODES] = run;
}

__global__ void __launch_bounds__(256) scatter_kernel(
    const int* __restrict__ ei, int* __restrict__ cursor, int* __restrict__ srcs)
{
    int e = blockIdx.x * blockDim.x + threadIdx.x;
    if (e >= N_EDGES) return;
    int src = __ldg(&ei[e]);
    int dst = __ldg(&ei[N_EDGES + e]);
    int pos = atomicAdd(&cursor[dst], 1);
    srcs[pos] = src;
}

// ============================================================================
// K agg+combine: Z[node] = relu((1+eps)*y[node] + sum_{src in CSR(node)} y[src] + preb)
// 16 threads per node (one float4 chunk each). No atomics; write-once.
// ============================================================================
__global__ void __launch_bounds__(256) agg_combine_kernel(
    const float* __restrict__ y, const int* __restrict__ start,
    const int* __restrict__ srcs, const float* __restrict__ epsp,
    const float* __restrict__ preb, float* __restrict__ z)
{
    const int tid = threadIdx.x;
    const int node = blockIdx.x * 16 + (tid >> 4);
    const int c4 = tid & 15;
    if (node >= N_NODES) return;

    const int s0 = __ldg(&start[node]);
    const int s1 = __ldg(&start[node + 1]);

    float4 acc = make_float4(0.f, 0.f, 0.f, 0.f);
    int j = s0;
    for (; j + 4 <= s1; j += 4) {
        int i0 = __ldg(&srcs[j + 0]);
        int i1 = __ldg(&srcs[j + 1]);
        int i2 = __ldg(&srcs[j + 2]);
        int i3 = __ldg(&srcs[j + 3]);
        float4 v0 = *(const float4*)(y + (size_t)i0 * 64 + c4 * 4);
        float4 v1 = *(const float4*)(y + (size_t)i1 * 64 + c4 * 4);
        float4 v2 = *(const float4*)(y + (size_t)i2 * 64 + c4 * 4);
        float4 v3 = *(const float4*)(y + (size_t)i3 * 64 + c4 * 4);
        acc.x += (v0.x + v1.x) + (v2.x + v3.x);
        acc.y += (v0.y + v1.y) + (v2.y + v3.y);
        acc.z += (v0.z + v1.z) + (v2.z + v3.z);
        acc.w += (v0.w + v1.w) + (v2.w + v3.w);
    }
    for (; j < s1; ++j) {
        int i0 = __ldg(&srcs[j]);
        float4 v0 = *(const float4*)(y + (size_t)i0 * 64 + c4 * 4);
        acc.x += v0.x; acc.y += v0.y; acc.z += v0.z; acc.w += v0.w;
    }

    const float epsf = 1.0f + __ldg(&epsp[0]);
    float4 self = *(const float4*)(y + (size_t)node * 64 + c4 * 4);
    float4 pb   = *(const float4*)(preb + c4 * 4);
    float4 o;
    o.x = fmaxf(fmaf(epsf, self.x, acc.x) + pb.x, 0.f);
    o.y = fmaxf(fmaf(epsf, self.y, acc.y) + pb.y, 0.f);
    o.z = fmaxf(fmaf(epsf, self.z, acc.z) + pb.z, 0.f);
    o.w = fmaxf(fmaf(epsf, self.w, acc.w) + pb.w, 0.f);
    *(float4*)(z + (size_t)node * 64 + c4 * 4) = o;
}

// ============================================================================
// K gemm 64x64:  out = EPI ? relu(A@W + bias) : A@W
// ============================================================================
template <bool EPI>
__global__ void __launch_bounds__(256) gemm64_kernel(
    const float* __restrict__ A, const float* __restrict__ W,
    const float* __restrict__ bias, float* __restrict__ out)
{
    __shared__ float sX[64][68];
    __shared__ float sW[64][64];

    const int tid = threadIdx.x;
    const int tc = tid & 15;
    const int tr = tid >> 4;
    const int row0 = blockIdx.x * 64;

#pragma unroll
    for (int i = 0; i < 16; ++i) {
        int idx = tid + i * 256;
        sW[idx >> 6][idx & 63] = W[idx];
    }
#pragma unroll
    for (int i = 0; i < 16; ++i) {
        int idx = tid + i * 256;
        int r = idx >> 6, kk = idx & 63;
        int row = row0 + r;
        sX[r][kk] = (row < N_NODES) ? A[(size_t)row * 64 + kk] : 0.f;
    }
    __syncthreads();

    float acc[4][4] = {};
#pragma unroll
    for (int k = 0; k < 64; k += 4) {
        float4 wv0 = *(const float4*)&sW[k + 0][tc * 4];
        float4 wv1 = *(const float4*)&sW[k + 1][tc * 4];
        float4 wv2 = *(const float4*)&sW[k + 2][tc * 4];
        float4 wv3 = *(const float4*)&sW[k + 3][tc * 4];
#pragma unroll
        for (int i = 0; i < 4; ++i) {
            float4 xv = *(const float4*)&sX[tr * 4 + i][k];
            acc[i][0] += xv.x * wv0.x + xv.y * wv1.x + xv.z * wv2.x + xv.w * wv3.x;
            acc[i][1] += xv.x * wv0.y + xv.y * wv1.y + xv.z * wv2.y + xv.w * wv3.y;
            acc[i][2] += xv.x * wv0.z + xv.y * wv1.z + xv.z * wv2.z + xv.w * wv3.z;
            acc[i][3] += xv.x * wv0.w + xv.y * wv1.w + xv.z * wv2.w + xv.w * wv3.w;
        }
    }

#pragma unroll
    for (int i = 0; i < 4; ++i) {
        int row = row0 + tr * 4 + i;
        if (row < N_NODES) {
            float4 o = make_float4(acc[i][0], acc[i][1], acc[i][2], acc[i][3]);
            if (EPI) {
                const float4 bv = *(const float4*)&bias[tc * 4];
                o.x = fmaxf(o.x + bv.x, 0.f);
                o.y = fmaxf(o.y + bv.y, 0.f);
                o.z = fmaxf(o.z + bv.z, 0.f);
                o.w = fmaxf(o.w + bv.w, 0.f);
            }
            *(float4*)&out[(size_t)row * 64 + tc * 4] = o;
        }
    }
}

// ============================================================================
// K gemm+pool:  h = relu(A@W + bias); pooled[batch[row]] += h[row]
// ============================================================================
__global__ void __launch_bounds__(256) gemm_pool_kernel(
    const float* __restrict__ A, const float* __restrict__ W,
    const float* __restrict__ bias, const int* __restrict__ batch,
    float* __restrict__ pooled)
{
    __shared__ float sX[64][68];
    __shared__ float sW[64][64];

    const int tid = threadIdx.x;
    const int tc = tid & 15;
    const int tr = tid >> 4;
    const int row0 = blockIdx.x * 64;

#pragma unroll
    for (int i = 0; i < 16; ++i) {
        int idx = tid + i * 256;
        sW[idx >> 6][idx & 63] = W[idx];
    }
#pragma unroll
    for (int i = 0; i < 16; ++i) {
        int idx = tid + i * 256;
        int r = idx >> 6, kk = idx & 63;
        int row = row0 + r;
        sX[r][kk] = (row < N_NODES) ? A[(size_t)row * 64 + kk] : 0.f;
    }
    __syncthreads();

    float acc[4][4] = {};
#pragma unroll
    for (int k = 0; k < 64; k += 4) {
        float4 wv0 = *(const float4*)&sW[k + 0][tc * 4];
        float4 wv1 = *(const float4*)&sW[k + 1][tc * 4];
        float4 wv2 = *(const float4*)&sW[k + 2][tc * 4];
        float4 wv3 = *(const float4*)&sW[k + 3][tc * 4];
#pragma unroll
        for (int i = 0; i < 4; ++i) {
            float4 xv = *(const float4*)&sX[tr * 4 + i][k];
            acc[i][0] += xv.x * wv0.x + xv.y * wv1.x + xv.z * wv2.x + xv.w * wv3.x;
            acc[i][1] += xv.x * wv0.y + xv.y * wv1.y + xv.z * wv2.y + xv.w * wv3.y;
            acc[i][2] += xv.x * wv0.z + xv.y * wv1.z + xv.z * wv2.z + xv.w * wv3.z;
            acc[i][3] += xv.x * wv0.w + xv.y * wv1.w + xv.z * wv2.w + xv.w * wv3.w;
        }
    }

    const float4 bv = *(const float4*)&bias[tc * 4];
#pragma unroll
    for (int i = 0; i < 4; ++i) {
        int row = row0 + tr * 4 + i;
        if (row < N_NODES) {
            int g = __ldg(&batch[row]);
            float4 o;
            o.x = fmaxf(acc[i][0] + bv.x, 0.f);
            o.y = fmaxf(acc[i][1] + bv.y, 0.f);
            o.z = fmaxf(acc[i][2] + bv.z, 0.f);
            o.w = fmaxf(acc[i][3] + bv.w, 0.f);
            float* p = pooled + (size_t)g * 64 + tc * 4;
            asm volatile("red.global.add.v4.f32 [%0], {%1,%2,%3,%4};"
                         :: "l"(p), "f"(o.x), "f"(o.y), "f"(o.z), "f"(o.w) : "memory");
        }
    }
}

// ============================================================================
// head: logits + log_softmax
// ============================================================================
__global__ void __launch_bounds__(256) head_kernel(
    const float* __restrict__ pooled, const float* __restrict__ fcw,
    const float* __restrict__ fcb, float* __restrict__ out)
{
    int g = blockIdx.x * blockDim.x + threadIdx.x;
    if (g >= N_GRAPHS) return;
    float logit[OUT_CH];
#pragma unroll
    for (int j = 0; j < OUT_CH; ++j) logit[j] = __ldg(&fcb[j]);
#pragma unroll 8
    for (int k = 0; k < HID; ++k) {
        float p = pooled[g * HID + k];
#pragma unroll
        for (int j = 0; j < OUT_CH; ++j)
            logit[j] += p * __ldg(&fcw[k * OUT_CH + j]);
    }
    float m = logit[0];
#pragma unroll
    for (int j = 1; j < OUT_CH; ++j) m = fmaxf(m, logit[j]);
    float s = 0.f;
#pragma unroll
    for (int j = 0; j < OUT_CH; ++j) s += __expf(logit[j] - m);
    float ls = m + logf(s);
#pragma unroll
    for (int j = 0; j < OUT_CH; ++j) out[g * OUT_CH + j] = logit[j] - ls;
}

// ---------------- launch ----------------------------------------------------
extern "C" void kernel_launch(void* const* d_in, const int* in_sizes, int n_in,
                              void* d_out, int out_size)
{
    const float* x    = (const float*)d_in[0];
    const int*   ei   = (const int*)d_in[1];
    const int*   batch= (const int*)d_in[2];
    const float* eps0 = (const float*)d_in[3];
    const float* w0a  = (const float*)d_in[4];
    const float* b0a  = (const float*)d_in[5];
    const float* w0b  = (const float*)d_in[6];
    const float* b0b  = (const float*)d_in[7];
    const float* eps1 = (const float*)d_in[8];
    const float* w1a  = (const float*)d_in[9];
    const float* b1a  = (const float*)d_in[10];
    const float* w1b  = (const float*)d_in[11];
    const float* b1b  = (const float*)d_in[12];
    const float* fcw  = (const float*)d_in[13];
    const float* fcb  = (const float*)d_in[14];
    float*       out  = (float*)d_out;

    float *bufA, *bufZ, *bufT, *pooled;
    int *deg, *start, *cursor, *srcs;
    cudaGetSymbolAddress((void**)&bufA, g_bufA);
    cudaGetSymbolAddress((void**)&bufZ, g_bufZ);
    cudaGetSymbolAddress((void**)&bufT, g_bufT);
    cudaGetSymbolAddress((void**)&pooled, g_pooled);
    cudaGetSymbolAddress((void**)&deg, g_deg);
    cudaGetSymbolAddress((void**)&start, g_start);
    cudaGetSymbolAddress((void**)&cursor, g_cursor);
    cudaGetSymbolAddress((void**)&srcs, g_srcs);

    const int gemm_blocks = (N_NODES + 63) / 64;          // 782
    const int edge_blocks = (N_EDGES + 255) / 256;        // 3125
    const int agg_blocks  = (N_NODES + 15) / 16;          // 3125

    // K1: y0 = x @ w0a ; zero deg + pooled
    gemm_in_kernel<<<gemm_blocks, 256>>>(x, w0a, bufA, deg, pooled);
    // CSR build (overlaps nothing but is cheap)
    hist_kernel<<<edge_blocks, 256>>>(ei, deg);
    scan_kernel<<<1, 1024>>>(deg, start, cursor);
    scatter_kernel<<<edge_blocks, 256>>>(ei, cursor, srcs);

    // Layer 0
    agg_combine_kernel<<<agg_blocks, 256>>>(bufA, start, srcs, eps0, b0a, bufZ);
    gemm64_kernel<true><<<gemm_blocks, 256>>>(bufZ, w0b, b0b, bufT);
    gemm64_kernel<false><<<gemm_blocks, 256>>>(bufT, w1a, nullptr, bufA);

    // Layer 1
    agg_combine_kernel<<<agg_blocks, 256>>>(bufA, start, srcs, eps1, b1a, bufZ);
    gemm_pool_kernel<<<gemm_blocks, 256>>>(bufZ, w1b, b1b, batch, pooled);

    // Head
    head_kernel<<<2, 256>>>(pooled, fcw, fcb, out);
}

// round 5
// speedup vs baseline: 1.2001x; 1.1913x over previous
#include <cuda_runtime.h>

#define N_NODES  50000
#define N_EDGES  800000
#define IN_CH    128
#define HID      64
#define N_GRAPHS 512
#define OUT_CH   10

// ---------------- scratch (static device memory; no allocations) ------------
__device__ float g_bufA[N_NODES * HID];   // y (pre-agg features)
__device__ float g_bufB[N_NODES * HID];   // agg buffer (atomics target)
__device__ float g_bufC[N_NODES * HID];   // h0
__device__ float g_pooled[N_GRAPHS * HID];

// ============================================================================
// K1: y0 = x @ w0a  (K=128). Tail: zero agg buffer rows; block 0 zeroes pooled.
// ============================================================================
__global__ void __launch_bounds__(256) gemm_in_kernel(
    const float* __restrict__ A, const float* __restrict__ W,
    float* __restrict__ out, float* __restrict__ aggz, float* __restrict__ pooled)
{
    __shared__ float sX[64][68];
    __shared__ float sW[64][64];

    const int tid = threadIdx.x;
    const int tc = tid & 15;
    const int tr = tid >> 4;
    const int row0 = blockIdx.x * 64;

    float acc[4][4] = {};

    for (int kc = 0; kc < IN_CH; kc += 64) {
#pragma unroll
        for (int i = 0; i < 16; ++i) {
            int idx = tid + i * 256;
            sW[idx >> 6][idx & 63] = W[(kc + (idx >> 6)) * 64 + (idx & 63)];
        }
#pragma unroll
        for (int i = 0; i < 16; ++i) {
            int idx = tid + i * 256;
            int r = idx >> 6, kk = idx & 63;
            int row = row0 + r;
            sX[r][kk] = (row < N_NODES) ? A[(size_t)row * IN_CH + kc + kk] : 0.f;
        }
        __syncthreads();

#pragma unroll
        for (int k = 0; k < 64; k += 4) {
            float4 wv0 = *(const float4*)&sW[k + 0][tc * 4];
            float4 wv1 = *(const float4*)&sW[k + 1][tc * 4];
            float4 wv2 = *(const float4*)&sW[k + 2][tc * 4];
            float4 wv3 = *(const float4*)&sW[k + 3][tc * 4];
#pragma unroll
            for (int i = 0; i < 4; ++i) {
                float4 xv = *(const float4*)&sX[tr * 4 + i][k];
                acc[i][0] += xv.x * wv0.x + xv.y * wv1.x + xv.z * wv2.x + xv.w * wv3.x;
                acc[i][1] += xv.x * wv0.y + xv.y * wv1.y + xv.z * wv2.y + xv.w * wv3.y;
                acc[i][2] += xv.x * wv0.z + xv.y * wv1.z + xv.z * wv2.z + xv.w * wv3.z;
                acc[i][3] += xv.x * wv0.w + xv.y * wv1.w + xv.z * wv2.w + xv.w * wv3.w;
            }
        }
        __syncthreads();
    }

#pragma unroll
    for (int i = 0; i < 4; ++i) {
        int row = row0 + tr * 4 + i;
        if (row < N_NODES)
            *(float4*)&out[(size_t)row * 64 + tc * 4] =
                make_float4(acc[i][0], acc[i][1], acc[i][2], acc[i][3]);
    }

    // zero agg buffer rows for this block
    const float4 z4 = make_float4(0.f, 0.f, 0.f, 0.f);
#pragma unroll
    for (int i = 0; i < 4; ++i) {
        int idx = tid + i * 256;              // 1024 float4s = 64 rows * 16
        int row = row0 + (idx >> 4);
        if (row < N_NODES)
            *(float4*)&aggz[(size_t)row * 64 + (idx & 15) * 4] = z4;
    }
    if (blockIdx.x == 0) {
        for (int i = tid; i < N_GRAPHS * HID / 4; i += 256)
            ((float4*)pooled)[i] = z4;
    }
}

// ============================================================================
// K2/K5: edge aggregation with 8-edge batching per thread (MLP=8).
//   agg[dst] += y[src]  via red.global.add.v4.f32
// Thread layout: c4 = t & 15 (16B chunk), edges [(t>>4)*8, +8)
// ============================================================================
#define E_PER 8
__global__ void __launch_bounds__(256) edge_agg_kernel(
    const float* __restrict__ y, const int* __restrict__ ei,
    float* __restrict__ agg)
{
    const int t = blockIdx.x * blockDim.x + threadIdx.x;
    const int c4 = t & 15;
    const int eb = (t >> 4) * E_PER;
    if (eb >= N_EDGES) return;

    int s[E_PER], d[E_PER];
#pragma unroll
    for (int j = 0; j < E_PER; ++j) {
        s[j] = __ldg(&ei[eb + j]);
        d[j] = __ldg(&ei[N_EDGES + eb + j]);
    }
    float4 v[E_PER];
#pragma unroll
    for (int j = 0; j < E_PER; ++j)
        v[j] = *(const float4*)(y + (size_t)s[j] * 64 + c4 * 4);
#pragma unroll
    for (int j = 0; j < E_PER; ++j) {
        float* p = agg + (size_t)d[j] * 64 + c4 * 4;
        asm volatile("red.global.add.v4.f32 [%0], {%1,%2,%3,%4};"
                     :: "l"(p), "f"(v[j].x), "f"(v[j].y), "f"(v[j].z), "f"(v[j].w)
                     : "memory");
    }
}

// ============================================================================
// K3: combine + GEMM:  out = relu( relu((1+eps)*A + G + preb) @ W + bias )
// ============================================================================
__global__ void __launch_bounds__(256) combine_gemm_kernel(
    const float* __restrict__ A, const float* __restrict__ G,
    const float* __restrict__ epsp, const float* __restrict__ preb,
    const float* __restrict__ W, const float* __restrict__ bias,
    float* __restrict__ out)
{
    __shared__ float sX[64][68];
    __shared__ float sW[64][64];

    const int tid = threadIdx.x;
    const int tc = tid & 15;
    const int tr = tid >> 4;
    const int row0 = blockIdx.x * 64;
    const float epsf = 1.0f + __ldg(&epsp[0]);

#pragma unroll
    for (int i = 0; i < 16; ++i) {
        int idx = tid + i * 256;
        sW[idx >> 6][idx & 63] = W[idx];
    }
#pragma unroll
    for (int i = 0; i < 16; ++i) {
        int idx = tid + i * 256;
        int r = idx >> 6, kk = idx & 63;
        int row = row0 + r;
        float v = 0.f;
        if (row < N_NODES) {
            size_t off = (size_t)row * 64 + kk;
            v = fmaxf(fmaf(epsf, A[off], G[off]) + preb[kk], 0.f);
        }
        sX[r][kk] = v;
    }
    __syncthreads();

    float acc[4][4] = {};
#pragma unroll
    for (int k = 0; k < 64; k += 4) {
        float4 wv0 = *(const float4*)&sW[k + 0][tc * 4];
        float4 wv1 = *(const float4*)&sW[k + 1][tc * 4];
        float4 wv2 = *(const float4*)&sW[k + 2][tc * 4];
        float4 wv3 = *(const float4*)&sW[k + 3][tc * 4];
#pragma unroll
        for (int i = 0; i < 4; ++i) {
            float4 xv = *(const float4*)&sX[tr * 4 + i][k];
            acc[i][0] += xv.x * wv0.x + xv.y * wv1.x + xv.z * wv2.x + xv.w * wv3.x;
            acc[i][1] += xv.x * wv0.y + xv.y * wv1.y + xv.z * wv2.y + xv.w * wv3.y;
            acc[i][2] += xv.x * wv0.z + xv.y * wv1.z + xv.z * wv2.z + xv.w * wv3.z;
            acc[i][3] += xv.x * wv0.w + xv.y * wv1.w + xv.z * wv2.w + xv.w * wv3.w;
        }
    }

    const float4 bv = *(const float4*)&bias[tc * 4];
#pragma unroll
    for (int i = 0; i < 4; ++i) {
        int row = row0 + tr * 4 + i;
        if (row < N_NODES) {
            float4 o;
            o.x = fmaxf(acc[i][0] + bv.x, 0.f);
            o.y = fmaxf(acc[i][1] + bv.y, 0.f);
            o.z = fmaxf(acc[i][2] + bv.z, 0.f);
            o.w = fmaxf(acc[i][3] + bv.w, 0.f);
            *(float4*)&out[(size_t)row * 64 + tc * 4] = o;
        }
    }
}

// ============================================================================
// K4: plain GEMM 64x64: out = A @ W ; tail: re-zero agg buffer rows
// ============================================================================
__global__ void __launch_bounds__(256) gemm64_zero_kernel(
    const float* __restrict__ A, const float* __restrict__ W,
    float* __restrict__ out, float* __restrict__ aggz)
{
    __shared__ float sX[64][68];
    __shared__ float sW[64][64];

    const int tid = threadIdx.x;
    const int tc = tid & 15;
    const int tr = tid >> 4;
    const int row0 = blockIdx.x * 64;

#pragma unroll
    for (int i = 0; i < 16; ++i) {
        int idx = tid + i * 256;
        sW[idx >> 6][idx & 63] = W[idx];
    }
#pragma unroll
    for (int i = 0; i < 16; ++i) {
        int idx = tid + i * 256;
        int r = idx >> 6, kk = idx & 63;
        int row = row0 + r;
        sX[r][kk] = (row < N_NODES) ? A[(size_t)row * 64 + kk] : 0.f;
    }
    __syncthreads();

    float acc[4][4] = {};
#pragma unroll
    for (int k = 0; k < 64; k += 4) {
        float4 wv0 = *(const float4*)&sW[k + 0][tc * 4];
        float4 wv1 = *(const float4*)&sW[k + 1][tc * 4];
        float4 wv2 = *(const float4*)&sW[k + 2][tc * 4];
        float4 wv3 = *(const float4*)&sW[k + 3][tc * 4];
#pragma unroll
        for (int i = 0; i < 4; ++i) {
            float4 xv = *(const float4*)&sX[tr * 4 + i][k];
            acc[i][0] += xv.x * wv0.x + xv.y * wv1.x + xv.z * wv2.x + xv.w * wv3.x;
            acc[i][1] += xv.x * wv0.y + xv.y * wv1.y + xv.z * wv2.y + xv.w * wv3.y;
            acc[i][2] += xv.x * wv0.z + xv.y * wv1.z + xv.z * wv2.z + xv.w * wv3.z;
            acc[i][3] += xv.x * wv0.w + xv.y * wv1.w + xv.z * wv2.w + xv.w * wv3.w;
        }
    }

#pragma unroll
    for (int i = 0; i < 4; ++i) {
        int row = row0 + tr * 4 + i;
        if (row < N_NODES)
            *(float4*)&out[(size_t)row * 64 + tc * 4] =
                make_float4(acc[i][0], acc[i][1], acc[i][2], acc[i][3]);
    }

    const float4 z4 = make_float4(0.f, 0.f, 0.f, 0.f);
#pragma unroll
    for (int i = 0; i < 4; ++i) {
        int idx = tid + i * 256;
        int row = row0 + (idx >> 4);
        if (row < N_NODES)
            *(float4*)&aggz[(size_t)row * 64 + (idx & 15) * 4] = z4;
    }
}

// ============================================================================
// K6: combine + GEMM + pool:  h = relu(relu((1+eps)*A+G+preb) @ W + bias)
//     pooled[batch[row]] += h[row]   (h never hits global)
// ============================================================================
__global__ void __launch_bounds__(256) combine_gemm_pool_kernel(
    const float* __restrict__ A, const float* __restrict__ G,
    const float* __restrict__ epsp, const float* __restrict__ preb,
    const float* __restrict__ W, const float* __restrict__ bias,
    const int* __restrict__ batch, float* __restrict__ pooled)
{
    __shared__ float sX[64][68];
    __shared__ float sW[64][64];

    const int tid = threadIdx.x;
    const int tc = tid & 15;
    const int tr = tid >> 4;
    const int row0 = blockIdx.x * 64;
    const float epsf = 1.0f + __ldg(&epsp[0]);

#pragma unroll
    for (int i = 0; i < 16; ++i) {
        int idx = tid + i * 256;
        sW[idx >> 6][idx & 63] = W[idx];
    }
#pragma unroll
    for (int i = 0; i < 16; ++i) {
        int idx = tid + i * 256;
        int r = idx >> 6, kk = idx & 63;
        int row = row0 + r;
        float v = 0.f;
        if (row < N_NODES) {
            size_t off = (size_t)row * 64 + kk;
            v = fmaxf(fmaf(epsf, A[off], G[off]) + preb[kk], 0.f);
        }
        sX[r][kk] = v;
    }
    __syncthreads();

    float acc[4][4] = {};
#pragma unroll
    for (int k = 0; k < 64; k += 4) {
        float4 wv0 = *(const float4*)&sW[k + 0][tc * 4];
        float4 wv1 = *(const float4*)&sW[k + 1][tc * 4];
        float4 wv2 = *(const float4*)&sW[k + 2][tc * 4];
        float4 wv3 = *(const float4*)&sW[k + 3][tc * 4];
#pragma unroll
        for (int i = 0; i < 4; ++i) {
            float4 xv = *(const float4*)&sX[tr * 4 + i][k];
            acc[i][0] += xv.x * wv0.x + xv.y * wv1.x + xv.z * wv2.x + xv.w * wv3.x;
            acc[i][1] += xv.x * wv0.y + xv.y * wv1.y + xv.z * wv2.y + xv.w * wv3.y;
            acc[i][2] += xv.x * wv0.z + xv.y * wv1.z + xv.z * wv2.z + xv.w * wv3.z;
            acc[i][3] += xv.x * wv0.w + xv.y * wv1.w + xv.z * wv2.w + xv.w * wv3.w;
        }
    }

    const float4 bv = *(const float4*)&bias[tc * 4];
#pragma unroll
    for (int i = 0; i < 4; ++i) {
        int row = row0 + tr * 4 + i;
        if (row < N_NODES) {
            int g = __ldg(&batch[row]);
            float4 o;
            o.x = fmaxf(acc[i][0] + bv.x, 0.f);
            o.y = fmaxf(acc[i][1] + bv.y, 0.f);
            o.z = fmaxf(acc[i][2] + bv.z, 0.f);
            o.w = fmaxf(acc[i][3] + bv.w, 0.f);
            float* p = pooled + (size_t)g * 64 + tc * 4;
            asm volatile("red.global.add.v4.f32 [%0], {%1,%2,%3,%4};"
                         :: "l"(p), "f"(o.x), "f"(o.y), "f"(o.z), "f"(o.w) : "memory");
        }
    }
}

// ============================================================================
// K7: head: logits + log_softmax
// ============================================================================
__global__ void __launch_bounds__(256) head_kernel(
    const float* __restrict__ pooled, const float* __restrict__ fcw,
    const float* __restrict__ fcb, float* __restrict__ out)
{
    int g = blockIdx.x * blockDim.x + threadIdx.x;
    if (g >= N_GRAPHS) return;
    float logit[OUT_CH];
#pragma unroll
    for (int j = 0; j < OUT_CH; ++j) logit[j] = __ldg(&fcb[j]);
#pragma unroll 8
    for (int k = 0; k < HID; ++k) {
        float p = pooled[g * HID + k];
#pragma unroll
        for (int j = 0; j < OUT_CH; ++j)
            logit[j] += p * __ldg(&fcw[k * OUT_CH + j]);
    }
    float m = logit[0];
#pragma unroll
    for (int j = 1; j < OUT_CH; ++j) m = fmaxf(m, logit[j]);
    float s = 0.f;
#pragma unroll
    for (int j = 0; j < OUT_CH; ++j) s += __expf(logit[j] - m);
    float ls = m + logf(s);
#pragma unroll
    for (int j = 0; j < OUT_CH; ++j) out[g * OUT_CH + j] = logit[j] - ls;
}

// ---------------- launch ----------------------------------------------------
extern "C" void kernel_launch(void* const* d_in, const int* in_sizes, int n_in,
                              void* d_out, int out_size)
{
    const float* x    = (const float*)d_in[0];
    const int*   ei   = (const int*)d_in[1];
    const int*   batch= (const int*)d_in[2];
    const float* eps0 = (const float*)d_in[3];
    const float* w0a  = (const float*)d_in[4];
    const float* b0a  = (const float*)d_in[5];
    const float* w0b  = (const float*)d_in[6];
    const float* b0b  = (const float*)d_in[7];
    const float* eps1 = (const float*)d_in[8];
    const float* w1a  = (const float*)d_in[9];
    const float* b1a  = (const float*)d_in[10];
    const float* w1b  = (const float*)d_in[11];
    const float* b1b  = (const float*)d_in[12];
    const float* fcw  = (const float*)d_in[13];
    const float* fcb  = (const float*)d_in[14];
    float*       out  = (float*)d_out;

    float *bufA, *bufB, *bufC, *pooled;
    cudaGetSymbolAddress((void**)&bufA, g_bufA);
    cudaGetSymbolAddress((void**)&bufB, g_bufB);
    cudaGetSymbolAddress((void**)&bufC, g_bufC);
    cudaGetSymbolAddress((void**)&pooled, g_pooled);

    const int gemm_blocks = (N_NODES + 63) / 64;                     // 782
    const int edge_blocks = (N_EDGES / E_PER * 16 + 255) / 256;      // 6250

    // K1: y0 = x @ w0a ; zero bufB + pooled
    gemm_in_kernel<<<gemm_blocks, 256>>>(x, w0a, bufA, bufB, pooled);
    // K2: agg0 = scatter-add(y0), 8 edges/thread
    edge_agg_kernel<<<edge_blocks, 256>>>(bufA, ei, bufB);
    // K3: h0 = relu(relu(combine0) @ w0b + b0b)
    combine_gemm_kernel<<<gemm_blocks, 256>>>(bufA, bufB, eps0, b0a, w0b, b0b, bufC);
    // K4: y1 = h0 @ w1a ; re-zero bufB
    gemm64_zero_kernel<<<gemm_blocks, 256>>>(bufC, w1a, bufA, bufB);
    // K5: agg1 = scatter-add(y1)
    edge_agg_kernel<<<edge_blocks, 256>>>(bufA, ei, bufB);
    // K6: h1 = relu(relu(combine1) @ w1b + b1b) ; pool into pooled
    combine_gemm_pool_kernel<<<gemm_blocks, 256>>>(bufA, bufB, eps1, b1a, w1b, b1b, batch, pooled);
    // K7: logits + log_softmax
    head_kernel<<<2, 256>>>(pooled, fcw, fcb, out);
}